// round 14
// baseline (speedup 1.0000x reference)
#include <cuda_runtime.h>
#include <stdint.h>

// Sparse Adagrad on GB300 (sm_103a) — gather formulation, epoch-tagged buckets,
// two launches, zero clear passes.
//
//   m_new[v] = m[v] + sum_i g_i^2
//   w_new[v] = w[v] - lr * (sum_i g_i) / (sqrt(m_new[v]) + eps)
//
// g_head64[v] = (gen<<32)|(row+1). Entries tagged with an older generation
// read as empty, so the head array never needs clearing. g_gen is bumped by
// the LAST fused block to finish (completion counter), which is safe: the
// counter reaches nblocks-1 only after every block has already read gen, and
// launch boundaries order the bump before the next replay's build kernel.
//
// Fused kernel is the proven bandwidth shape: one float4 chunk per thread,
// 8M threads, evict-first loads/stores, regs<=32 -> 8 blocks/SM
// (82.8us @ ~6.15 TB/s measured).
//
// Output layout: out[0:V*D] = weights_new, out[V*D:2*V*D] = moments_new.
// indices arrive as int32 (JAX x64 disabled). valid_count=200000 static.

#define EPS 1e-10f
#define D 64
#define CHUNKS 16            // D/4 float4 chunks per row
#define VALID_COUNT 200000
#define V_MAX 500000
#define N_MAX 262144

__device__ unsigned long long g_head64[V_MAX]; // (gen<<32)|(row+1); zero-init
__device__ unsigned long long g_next64[N_MAX]; // previous head value
__device__ unsigned int g_gen;                 // current generation (0-init)
__device__ unsigned int g_done;                // fused completion counter (0-init)

__global__ void __launch_bounds__(256)
build_lists_kernel(const int* __restrict__ idx)
{
    int i = blockIdx.x * blockDim.x + threadIdx.x;
    if (i >= VALID_COUNT) return;
    unsigned int gen = *((volatile unsigned int*)&g_gen);
    int v = __ldg(&idx[i]);
    g_next64[i] = atomicExch(&g_head64[v],
                             ((unsigned long long)gen << 32) |
                             (unsigned long long)(i + 1));
}

__global__ void __launch_bounds__(256, 8)
fused_adagrad_kernel(const float4* __restrict__ g,   // [N, 16]
                     const float4* __restrict__ w,   // [V, 16]
                     const float4* __restrict__ m,   // [V, 16]
                     const float* __restrict__ lr_ptr,
                     float4* __restrict__ out_w,     // [V, 16]
                     float4* __restrict__ out_m,     // [V, 16]
                     int V, int nblocks)
{
    const unsigned int gen = *((volatile unsigned int*)&g_gen);

    long t = (long)blockIdx.x * blockDim.x + threadIdx.x;
    long total = (long)V * CHUNKS;
    if (t < total) {
        int v = (int)(t >> 4);        // output row
        int chunk = (int)(t & 15);
        long off = (long)v * CHUNKS + chunk;

        float lr = __ldg(lr_ptr);
        // Touch-once streaming loads (evict-first keeps L2 for g + metadata).
        float4 mv = __ldcs(&m[off]);
        float4 wv = __ldcs(&w[off]);

        unsigned long long e = g_head64[v];   // broadcast across row's lanes
        if ((unsigned int)(e >> 32) == gen && (unsigned int)e != 0u) {
            float4 sg  = make_float4(0.f, 0.f, 0.f, 0.f);
            float4 sg2 = make_float4(0.f, 0.f, 0.f, 0.f);
            do {
                int i = (int)((unsigned int)e) - 1;
                float4 gv = g[(long)i * CHUNKS + chunk];
                sg.x += gv.x;  sg.y += gv.y;  sg.z += gv.z;  sg.w += gv.w;
                sg2.x = fmaf(gv.x, gv.x, sg2.x);
                sg2.y = fmaf(gv.y, gv.y, sg2.y);
                sg2.z = fmaf(gv.z, gv.z, sg2.z);
                sg2.w = fmaf(gv.w, gv.w, sg2.w);
                e = g_next64[i];
            } while ((unsigned int)(e >> 32) == gen && (unsigned int)e != 0u);

            mv.x += sg2.x;  mv.y += sg2.y;  mv.z += sg2.z;  mv.w += sg2.w;

            wv.x -= lr * sg.x / (sqrtf(mv.x) + EPS);
            wv.y -= lr * sg.y / (sqrtf(mv.y) + EPS);
            wv.z -= lr * sg.z / (sqrtf(mv.z) + EPS);
            wv.w -= lr * sg.w / (sqrtf(mv.w) + EPS);
        }

        __stcs(&out_w[off], wv);
        __stcs(&out_m[off], mv);
    }

    // Last block to FINISH bumps the generation for the next launch/replay.
    // Every block read gen at entry, and the counter can only reach
    // nblocks-1 after all blocks are done, so no block can observe the bump
    // within this launch.
    __syncthreads();
    if (threadIdx.x == 0) {
        __threadfence();
        unsigned int prev = atomicAdd(&g_done, 1u);
        if (prev == (unsigned int)nblocks - 1u) {
            atomicExch(&g_done, 0u);
            __threadfence();
            atomicAdd(&g_gen, 1u);
        }
    }
}

extern "C" void kernel_launch(void* const* d_in, const int* in_sizes, int n_in,
                              void* d_out, int out_size)
{
    const float* gradients = (const float*)d_in[0];   // [N, 64]
    const float* weights   = (const float*)d_in[1];   // [V, 64]
    const float* moments   = (const float*)d_in[2];   // [V, 64]
    const int*   indices   = (const int*)d_in[3];     // [N] int32
    const float* lr        = (const float*)d_in[4];   // scalar

    long VD = (long)in_sizes[1];          // V*D = 32,000,000
    int  V  = (int)(VD / D);              // 500,000
    float* out_w = (float*)d_out;
    float* out_m = (float*)d_out + VD;

    // 1. build epoch-tagged per-bucket linked lists (no clear needed)
    build_lists_kernel<<<(VALID_COUNT + 255) / 256, 256>>>(indices);

    // 2. fused gather + update + write (single full pass over output)
    {
        long total = (long)V * CHUNKS;    // 8M threads
        int threads = 256;
        int blocks = (int)((total + threads - 1) / threads);
        fused_adagrad_kernel<<<blocks, threads>>>((const float4*)gradients,
                                                  (const float4*)weights,
                                                  (const float4*)moments,
                                                  lr,
                                                  (float4*)out_w,
                                                  (float4*)out_m,
                                                  V, blocks);
    }
}

// round 15
// speedup vs baseline: 1.0443x; 1.0443x over previous
#include <cuda_runtime.h>
#include <stdint.h>

// Sparse Adagrad on GB300 (sm_103a) — gather formulation, epoch-tagged buckets.
// TWO launches, zero clear passes, no fences, no volatile hot loads.
//
//   m_new[v] = m[v] + sum_i g_i^2
//   w_new[v] = w[v] - lr * (sum_i g_i) / (sqrt(m_new[v]) + eps)
//
// g_head64[v] = (gen<<32)|(row+1). Entries tagged with an older generation
// read as empty -> head array never needs clearing (zero-init == gen 0 with
// row 0 == empty). gen is read ONCE PER BLOCK (plain load, shared broadcast)
// — the R14 regression came from 8M per-thread volatile reads of one address.
// The fused kernel's last-finishing block bumps gen via a completion counter;
// no threadfence needed: each block's counter-add is program-ordered after
// its gen read, and the launch boundary orders the bump before the next
// replay's build kernel.
//
// Fused body is the proven bandwidth shape: one float4 chunk per thread,
// 8M threads, evict-first loads/stores, regs<=32 -> 8 blocks/SM
// (82.8us @ ~6.15 TB/s measured).
//
// Output layout: out[0:V*D] = weights_new, out[V*D:2*V*D] = moments_new.
// indices arrive as int32 (JAX x64 disabled). valid_count=200000 static.

#define EPS 1e-10f
#define D 64
#define CHUNKS 16            // D/4 float4 chunks per row
#define VALID_COUNT 200000
#define V_MAX 500000
#define N_MAX 262144

__device__ unsigned long long g_head64[V_MAX]; // (gen<<32)|(row+1); zero-init
__device__ unsigned long long g_next64[N_MAX]; // previous head value
__device__ unsigned int g_gen;                 // current generation (0-init)
__device__ unsigned int g_done;                // completion counter (0-init)

__global__ void __launch_bounds__(256)
build_lists_kernel(const int* __restrict__ idx)
{
    __shared__ unsigned int s_gen;
    if (threadIdx.x == 0) s_gen = g_gen;       // one plain load per block
    __syncthreads();

    int i = blockIdx.x * blockDim.x + threadIdx.x;
    if (i >= VALID_COUNT) return;
    int v = __ldg(&idx[i]);
    g_next64[i] = atomicExch(&g_head64[v],
                             ((unsigned long long)s_gen << 32) |
                             (unsigned long long)(i + 1));
}

__global__ void __launch_bounds__(256, 8)
fused_adagrad_kernel(const float4* __restrict__ g,   // [N, 16]
                     const float4* __restrict__ w,   // [V, 16]
                     const float4* __restrict__ m,   // [V, 16]
                     const float* __restrict__ lr_ptr,
                     float4* __restrict__ out_w,     // [V, 16]
                     float4* __restrict__ out_m,     // [V, 16]
                     int V, int nblocks)
{
    __shared__ unsigned int s_gen;
    if (threadIdx.x == 0) s_gen = g_gen;       // one plain load per block
    __syncthreads();
    const unsigned int gen = s_gen;

    long t = (long)blockIdx.x * blockDim.x + threadIdx.x;
    long total = (long)V * CHUNKS;
    if (t < total) {
        int v = (int)(t >> 4);        // output row
        int chunk = (int)(t & 15);
        long off = (long)v * CHUNKS + chunk;

        float lr = __ldg(lr_ptr);
        // Touch-once streaming loads (evict-first keeps L2 for g + metadata).
        float4 mv = __ldcs(&m[off]);
        float4 wv = __ldcs(&w[off]);

        unsigned long long e = g_head64[v];   // broadcast across row's lanes
        if ((unsigned int)(e >> 32) == gen && (unsigned int)e != 0u) {
            float4 sg  = make_float4(0.f, 0.f, 0.f, 0.f);
            float4 sg2 = make_float4(0.f, 0.f, 0.f, 0.f);
            do {
                int i = (int)((unsigned int)e) - 1;
                float4 gv = g[(long)i * CHUNKS + chunk];
                sg.x += gv.x;  sg.y += gv.y;  sg.z += gv.z;  sg.w += gv.w;
                sg2.x = fmaf(gv.x, gv.x, sg2.x);
                sg2.y = fmaf(gv.y, gv.y, sg2.y);
                sg2.z = fmaf(gv.z, gv.z, sg2.z);
                sg2.w = fmaf(gv.w, gv.w, sg2.w);
                e = g_next64[i];
            } while ((unsigned int)(e >> 32) == gen && (unsigned int)e != 0u);

            mv.x += sg2.x;  mv.y += sg2.y;  mv.z += sg2.z;  mv.w += sg2.w;

            wv.x -= lr * sg.x / (sqrtf(mv.x) + EPS);
            wv.y -= lr * sg.y / (sqrtf(mv.y) + EPS);
            wv.z -= lr * sg.z / (sqrtf(mv.z) + EPS);
            wv.w -= lr * sg.w / (sqrtf(mv.w) + EPS);
        }

        __stcs(&out_w[off], wv);
        __stcs(&out_m[off], mv);
    }

    // Gen bump: last block to finish increments g_gen for the next replay.
    // No fence needed — each block's counter-add is program-ordered after its
    // gen read, the bump fires only after all blocks have added, and the
    // launch boundary publishes it to the next replay's build kernel.
    __syncthreads();
    if (threadIdx.x == 0) {
        unsigned int prev = atomicAdd(&g_done, 1u);
        if (prev == (unsigned int)nblocks - 1u) {
            atomicExch(&g_done, 0u);
            atomicAdd(&g_gen, 1u);
        }
    }
}

extern "C" void kernel_launch(void* const* d_in, const int* in_sizes, int n_in,
                              void* d_out, int out_size)
{
    const float* gradients = (const float*)d_in[0];   // [N, 64]
    const float* weights   = (const float*)d_in[1];   // [V, 64]
    const float* moments   = (const float*)d_in[2];   // [V, 64]
    const int*   indices   = (const int*)d_in[3];     // [N] int32
    const float* lr        = (const float*)d_in[4];   // scalar

    long VD = (long)in_sizes[1];          // V*D = 32,000,000
    int  V  = (int)(VD / D);              // 500,000
    float* out_w = (float*)d_out;
    float* out_m = (float*)d_out + VD;

    // 1. build epoch-tagged per-bucket linked lists (no clear needed)
    build_lists_kernel<<<(VALID_COUNT + 255) / 256, 256>>>(indices);

    // 2. fused gather + update + write (single full pass over output)
    {
        long total = (long)V * CHUNKS;    // 8M threads
        int threads = 256;
        int blocks = (int)((total + threads - 1) / threads);
        fused_adagrad_kernel<<<blocks, threads>>>((const float4*)gradients,
                                                  (const float4*)weights,
                                                  (const float4*)moments,
                                                  lr,
                                                  (float4*)out_w,
                                                  (float4*)out_m,
                                                  V, blocks);
    }
}

// round 17
// speedup vs baseline: 1.3142x; 1.2584x over previous
#include <cuda_runtime.h>
#include <stdint.h>

// Sparse Adagrad on GB300 (sm_103a) — gather formulation, 3 launches.
// (Epoch-tagged variants abandoned: their end-of-kernel barrier/counter tail
//  blocks per-warp retirement and collapses DRAM% 77->58. No sync after the
//  streaming body, ever.)
//
//   m_new[v] = m[v] + sum_i g_i^2
//   w_new[v] = w[v] - lr * (sum_i g_i) / (sqrt(m_new[v]) + eps)
//
// Inverse index map as per-bucket linked lists: g_head[v] = row+1, 0 = empty.
// init clears heads (and warms L2 for build's atomics), build exchanges,
// fused gathers + updates + writes in one full streaming pass
// (proven shape: one float4 chunk/thread, regs<=32 -> 8 blocks/SM,
//  82.8us @ ~6.15 TB/s).
//
// Output layout: out[0:V*D] = weights_new, out[V*D:2*V*D] = moments_new.
// indices arrive as int32 (JAX x64 disabled). valid_count=200000 static.

#define EPS 1e-10f
#define D 64
#define CHUNKS 16            // D/4 float4 chunks per row
#define VALID_COUNT 200000
#define V_MAX 500000
#define N_MAX 262144

__device__ int g_head[V_MAX];   // 0 = empty, else gradient_row+1
__device__ int g_next[N_MAX];   // same encoding: old head value

// One-wave init: 123 blocks x 1024 threads, one int4 store per thread.
// (Init cost is dispatch-ramp-dominated, not traffic: fewer blocks = faster.)
__global__ void __launch_bounds__(1024)
init_head_kernel(int n4)        // n4 = V/4 int4 elements
{
    int i = blockIdx.x * 1024 + threadIdx.x;
    if (i < n4)
        reinterpret_cast<int4*>(g_head)[i] = make_int4(0, 0, 0, 0);
}

__global__ void __launch_bounds__(256)
build_lists_kernel(const int* __restrict__ idx)
{
    int i = blockIdx.x * blockDim.x + threadIdx.x;
    if (i >= VALID_COUNT) return;
    int v = __ldg(&idx[i]);
    g_next[i] = atomicExch(&g_head[v], i + 1);
}

__global__ void __launch_bounds__(256, 8)
fused_adagrad_kernel(const float4* __restrict__ g,   // [N, 16]
                     const float4* __restrict__ w,   // [V, 16]
                     const float4* __restrict__ m,   // [V, 16]
                     const float* __restrict__ lr_ptr,
                     float4* __restrict__ out_w,     // [V, 16]
                     float4* __restrict__ out_m,     // [V, 16]
                     int V)
{
    // 32-bit arithmetic throughout: V*CHUNKS = 8M < 2^31, byte offsets < 2^31.
    unsigned int t = blockIdx.x * 256u + threadIdx.x;
    unsigned int total = (unsigned int)V * CHUNKS;
    if (t >= total) return;
    int v = (int)(t >> 4);        // output row
    unsigned int off = t;         // == v*CHUNKS + chunk (identity mapping)
    unsigned int chunk = t & 15u;

    float lr = __ldg(lr_ptr);
    // Touch-once streaming loads (evict-first).
    float4 mv = __ldcs(&m[off]);
    float4 wv = __ldcs(&w[off]);

    int e = __ldcs(&g_head[v]);   // read exactly once per row
    if (e > 0) {
        float4 sg  = make_float4(0.f, 0.f, 0.f, 0.f);
        float4 sg2 = make_float4(0.f, 0.f, 0.f, 0.f);
        do {
            unsigned int i = (unsigned int)(e - 1);
            // each gradient row belongs to exactly one chain -> touch-once
            float4 gv = __ldcs(&g[i * CHUNKS + chunk]);
            sg.x += gv.x;  sg.y += gv.y;  sg.z += gv.z;  sg.w += gv.w;
            sg2.x = fmaf(gv.x, gv.x, sg2.x);
            sg2.y = fmaf(gv.y, gv.y, sg2.y);
            sg2.z = fmaf(gv.z, gv.z, sg2.z);
            sg2.w = fmaf(gv.w, gv.w, sg2.w);
            e = __ldcs(&g_next[i]);
        } while (e > 0);

        mv.x += sg2.x;  mv.y += sg2.y;  mv.z += sg2.z;  mv.w += sg2.w;

        wv.x -= lr * sg.x / (sqrtf(mv.x) + EPS);
        wv.y -= lr * sg.y / (sqrtf(mv.y) + EPS);
        wv.z -= lr * sg.z / (sqrtf(mv.z) + EPS);
        wv.w -= lr * sg.w / (sqrtf(mv.w) + EPS);
    }

    __stcs(&out_w[off], wv);
    __stcs(&out_m[off], mv);
    // no barrier, no counter: warps retire independently
}

extern "C" void kernel_launch(void* const* d_in, const int* in_sizes, int n_in,
                              void* d_out, int out_size)
{
    const float* gradients = (const float*)d_in[0];   // [N, 64]
    const float* weights   = (const float*)d_in[1];   // [V, 64]
    const float* moments   = (const float*)d_in[2];   // [V, 64]
    const int*   indices   = (const int*)d_in[3];     // [N] int32
    const float* lr        = (const float*)d_in[4];   // scalar

    long VD = (long)in_sizes[1];          // V*D = 32,000,000
    int  V  = (int)(VD / D);              // 500,000
    float* out_w = (float*)d_out;
    float* out_m = (float*)d_out + VD;

    // 1. clear bucket heads in one wave (2 MB; warms L2 for build's atomics)
    {
        int n4 = V / 4;                   // 125,000
        int blocks = (n4 + 1023) / 1024;  // 123 blocks
        init_head_kernel<<<blocks, 1024>>>(n4);
    }

    // 2. build per-bucket linked lists over valid gradient rows
    build_lists_kernel<<<(VALID_COUNT + 255) / 256, 256>>>(indices);

    // 3. fused gather + update + write (single full pass over output)
    {
        unsigned int total = (unsigned int)V * CHUNKS;   // 8M threads
        int blocks = (int)((total + 255u) / 256u);       // 31250
        fused_adagrad_kernel<<<blocks, 256>>>((const float4*)gradients,
                                              (const float4*)weights,
                                              (const float4*)moments,
                                              lr,
                                              (float4*)out_w,
                                              (float4*)out_m,
                                              V);
    }
}